// round 12
// baseline (speedup 1.0000x reference)
#include <cuda_runtime.h>
#include <cuda_bf16.h>
#include <cuda_fp16.h>

// Problem constants (HawkesIntensityFunction: B=2, N=4096, D=256)
#define BATCH 2
#define NLEN  4096
#define DM    256
#define LOG2E 1.4426950408889634f

#define ROWS_PB 512          // rows per block (2 per thread, 256 threads)
#define TJ      64           // j-tile size (events in smem)
#define RT_CNT  (NLEN / ROWS_PB)             // 8 row tiles per batch
#define JT_CNT  (NLEN / TJ)                  // 64 j tiles per batch
#define BLOCKS_PER_BATCH 288                 // sum_{rt=0..7} (64 - 8*rt)

__device__ __forceinline__ float ex2_approx(float x) {
    float r; asm("ex2.approx.f32 %0, %1;" : "=f"(r) : "f"(x)); return r;
}
__device__ __forceinline__ float sqrt_approx(float x) {
    float r; asm("sqrt.approx.f32 %0, %1;" : "=f"(r) : "f"(x)); return r;
}

// Packed per-event: (x, y, u = -beta*log2e*t, -u)
// Pair term for j>i:  alpha * 2^{u_i} * 2^{ng2*dist_ij - u_j}
__device__ float4 g_packed[BATCH * NLEN];

// ---------------------------------------------------------------------------
// Kernel 1: base intensity + packing.  One warp per row (8192 rows).
// out[row] = mu + exp(dot+b) + alpha*(i+1)   (closed form of the j<=i masked
// entries: triu mask applied BEFORE exp -> each contributes exp(0)*exp(0)=1).
// ---------------------------------------------------------------------------
__global__ __launch_bounds__(256)
void hawkes_setup_kernel(const float* __restrict__ z,
                         const float* __restrict__ t,
                         const float* __restrict__ loc,
                         const float* __restrict__ w,
                         const float* __restrict__ bias,
                         const float* __restrict__ mu,
                         const float* __restrict__ alpha,
                         const float* __restrict__ beta,
                         float* __restrict__ out)
{
    const int lane = threadIdx.x & 31;
    const int g    = blockIdx.x * 8 + (threadIdx.x >> 5);  // row id 0..8191
    const int i    = g & (NLEN - 1);

    const float4* wr = (const float4*)w;
    const float4  w0 = __ldg(wr + lane * 2 + 0);
    const float4  w1 = __ldg(wr + lane * 2 + 1);

    const float4* zr = (const float4*)(z + (size_t)g * DM);
    const float4  a0 = __ldg(zr + lane * 2 + 0);
    const float4  a1 = __ldg(zr + lane * 2 + 1);

    float dotp;
    dotp = a0.x * w0.x;
    dotp = fmaf(a0.y, w0.y, dotp);
    dotp = fmaf(a0.z, w0.z, dotp);
    dotp = fmaf(a0.w, w0.w, dotp);
    dotp = fmaf(a1.x, w1.x, dotp);
    dotp = fmaf(a1.y, w1.y, dotp);
    dotp = fmaf(a1.z, w1.z, dotp);
    dotp = fmaf(a1.w, w1.w, dotp);

    #pragma unroll
    for (int off = 16; off > 0; off >>= 1)
        dotp += __shfl_xor_sync(0xffffffffu, dotp, off);

    if (lane == 0) {
        const float muv = __ldg(mu);
        const float av  = __ldg(alpha);
        const float bv  = __ldg(bias);
        const float nb2 = -__ldg(beta) * LOG2E;

        const float base = ex2_approx((dotp + bv) * LOG2E);
        out[g] = muv + base + av * (float)(i + 1);

        const float2 lv = ((const float2*)loc)[g];
        const float  u  = nb2 * __ldg(t + g);
        g_packed[g] = make_float4(lv.x, lv.y, u, -u);
    }
}

// ex2 argument for one pair: ng2*dist - u_j   (2 FADD + FMUL + FFMA + MUFU.SQRT + FFMA)
__device__ __forceinline__ float pair_arg(float px, float py, float ng2,
                                          const float4& v)
{
    const float dx = px - v.x;
    const float dy = py - v.y;
    const float sq = fmaf(dx, dx, dy * dy);
    return fmaf(ng2, sqrt_approx(sq), v.w);
}

// two args -> one MUFU via ex2.approx.f16x2
__device__ __forceinline__ float2 ex2_pair(float a, float b)
{
    const __half2 h = h2exp2(__floats2half2_rn(a, b));
    return __half22float2(h);
}

// ---------------------------------------------------------------------------
// Kernel 2: pair excitation, tiled. Block = 256 threads = 512 rows (2/thread),
// j-tile of 64 events in smem. 576 blocks -> 4608 warps (occ ~47%).
// Per inner iteration: 4 pair terms = 4 MUFU.SQRT + 2 MUFU ex2.f16x2
// -> 1.5 MUFU per pair (was 2).
// ---------------------------------------------------------------------------
__global__ __launch_bounds__(256)
void hawkes_pairs_kernel(const float* __restrict__ alpha,
                         const float* __restrict__ gamma,
                         float* __restrict__ out)
{
    __shared__ float4 tile[TJ];

    // decode (b, rt, jt) from blockIdx.x; jt >= 8*rt (triangular tile set)
    int x = blockIdx.x;
    int b = 0;
    if (x >= BLOCKS_PER_BATCH) { b = 1; x -= BLOCKS_PER_BATCH; }
    int rt = 0;
    #pragma unroll
    for (int k = 0; k < RT_CNT; k++) {
        const int w_k = JT_CNT - 8 * k;      // tiles in row-band k
        if (x >= w_k && rt == k) { x -= w_k; rt = k + 1; }
    }
    const int jt = 8 * rt + x;

    const float av  = __ldg(alpha);
    const float ng2 = -__ldg(gamma) * LOG2E;

    const float4* pk = g_packed + b * NLEN;
    const int tid     = threadIdx.x;
    const int rowbase = rt * ROWS_PB;
    const int jbase   = jt * TJ;

    if (tid < TJ) tile[tid] = __ldg(pk + jbase + tid);
    __syncthreads();

    const int i0 = rowbase + tid;          // row A
    const int i1 = i0 + 256;               // row B
    const float4 p0 = pk[i0];
    const float4 p1 = pk[i1];

    float a00 = 0.0f, a01 = 0.0f;          // row A accumulators
    float a10 = 0.0f, a11 = 0.0f;          // row B accumulators

    if (jbase >= rowbase + ROWS_PB) {
        // interior tile: every j > every i in this block, no masking
        #pragma unroll 4
        for (int jj = 0; jj < TJ; jj += 2) {
            const float4 v0 = tile[jj + 0];
            const float4 v1 = tile[jj + 1];
            const float r00 = pair_arg(p0.x, p0.y, ng2, v0);
            const float r01 = pair_arg(p0.x, p0.y, ng2, v1);
            const float r10 = pair_arg(p1.x, p1.y, ng2, v0);
            const float r11 = pair_arg(p1.x, p1.y, ng2, v1);
            const float2 e0 = ex2_pair(r00, r01);   // one MUFU, two exps
            const float2 e1 = ex2_pair(r10, r11);
            a00 += e0.x;  a01 += e0.y;
            a10 += e1.x;  a11 += e1.y;
        }
    } else {
        // diagonal band: same math, predicated accumulate (j > i strictly)
        #pragma unroll 2
        for (int jj = 0; jj < TJ; jj += 2) {
            const int jg0 = jbase + jj;
            const int jg1 = jg0 + 1;
            const float4 v0 = tile[jj + 0];
            const float4 v1 = tile[jj + 1];
            const float r00 = pair_arg(p0.x, p0.y, ng2, v0);
            const float r01 = pair_arg(p0.x, p0.y, ng2, v1);
            const float r10 = pair_arg(p1.x, p1.y, ng2, v0);
            const float r11 = pair_arg(p1.x, p1.y, ng2, v1);
            const float2 e0 = ex2_pair(r00, r01);
            const float2 e1 = ex2_pair(r10, r11);
            if (jg0 > i0) a00 += e0.x;
            if (jg1 > i0) a01 += e0.y;
            if (jg0 > i1) a10 += e1.x;
            if (jg1 > i1) a11 += e1.y;
        }
    }

    const float s0 = ex2_approx(p0.z);     // 2^{u_i0}
    const float s1 = ex2_approx(p1.z);     // 2^{u_i1}
    atomicAdd(out + b * NLEN + i0, av * s0 * (a00 + a01));
    atomicAdd(out + b * NLEN + i1, av * s1 * (a10 + a11));
}

extern "C" void kernel_launch(void* const* d_in, const int* in_sizes, int n_in,
                              void* d_out, int out_size)
{
    const float* z     = (const float*)d_in[0];
    const float* t     = (const float*)d_in[1];
    const float* loc   = (const float*)d_in[2];
    const float* w     = (const float*)d_in[3];
    const float* bias  = (const float*)d_in[4];
    const float* mu    = (const float*)d_in[5];
    const float* alpha = (const float*)d_in[6];
    const float* beta  = (const float*)d_in[7];
    const float* gamma = (const float*)d_in[8];
    float* out = (float*)d_out;

    // Kernel 1: 8192 rows, 1 warp/row -> 1024 blocks of 256
    hawkes_setup_kernel<<<1024, 256>>>(z, t, loc, w, bias, mu, alpha, beta, out);
    // Kernel 2: 2 * 288 triangular tiles
    hawkes_pairs_kernel<<<2 * BLOCKS_PER_BATCH, 256>>>(alpha, gamma, out);
}

// round 13
// speedup vs baseline: 1.1246x; 1.1246x over previous
#include <cuda_runtime.h>
#include <cuda_bf16.h>

// Problem constants (HawkesIntensityFunction: B=2, N=4096, D=256)
#define BATCH 2
#define NLEN  4096
#define DM    256
#define LOG2E 1.4426950408889634f

#define ROWS_PB 256          // rows per block (== blockDim.x)
#define TJ      64           // j-tile size (events in smem)
#define RT_CNT  (NLEN / ROWS_PB)             // 16 row tiles per batch
#define JT_CNT  (NLEN / TJ)                  // 64 j tiles per batch
#define BLOCKS_PER_BATCH 544                 // sum_{rt=0..15} (64 - 4*rt)
#define GRID_K1 (2 * BLOCKS_PER_BATCH)       // 1088

__device__ __forceinline__ float ex2_approx(float x) {
    float r; asm("ex2.approx.f32 %0, %1;" : "=f"(r) : "f"(x)); return r;
}
__device__ __forceinline__ float sqrt_approx(float x) {
    float r; asm("sqrt.approx.f32 %0, %1;" : "=f"(r) : "f"(x)); return r;
}

// Scratch: base-intensity dots and excitation accumulators.
// g_excite is statically zero-initialized; the combine kernel re-zeroes it
// after consuming, so every graph replay starts from zeros (deterministic).
__device__ float g_base[BATCH * NLEN];
__device__ float g_excite[BATCH * NLEN];

// pair term vs tile event v for row at (px,py): 2^{ng2*dist - u_j}
// (v.w = -u_j; the per-row 2^{u_i} factor is applied in the combine kernel)
__device__ __forceinline__ float pair_term(float px, float py, float ng2,
                                           const float4& v)
{
    const float dx = px - v.x;
    const float dy = py - v.y;
    const float sq = fmaf(dx, dx, dy * dy);
    return ex2_approx(fmaf(ng2, sqrt_approx(sq), v.w));
}

// ---------------------------------------------------------------------------
// K1: fused pairs + base-intensity dots.
// Grid = 1088 triangular tiles (R7 config: 256 rows/block, TJ=64).
// Blocks 0..1023 additionally compute base dots for rows blockIdx*8+warp
// (z loads issued BEFORE the pair loop; consumed after -> latency hidden).
// Pair sums accumulate into g_excite via atomicAdd (raw, unscaled).
// ---------------------------------------------------------------------------
__global__ __launch_bounds__(256)
void hawkes_fused_kernel(const float* __restrict__ z,
                         const float* __restrict__ t,
                         const float* __restrict__ loc,
                         const float* __restrict__ w,
                         const float* __restrict__ beta,
                         const float* __restrict__ gamma)
{
    __shared__ float4 tile[TJ];

    const int tid  = threadIdx.x;
    const int lane = tid & 31;
    const int warp = tid >> 5;

    // ---- decode (b, rt, jt); jt >= 4*rt (triangular tile set) ----
    int x = blockIdx.x;
    int b = 0;
    if (x >= BLOCKS_PER_BATCH) { b = 1; x -= BLOCKS_PER_BATCH; }
    int rt = 0;
    #pragma unroll
    for (int k = 0; k < RT_CNT; k++) {
        const int w_k = JT_CNT - 4 * k;
        if (x >= w_k && rt == k) { x -= w_k; rt = k + 1; }
    }
    const int jt = 4 * rt + x;

    const float ng2 = -__ldg(gamma) * LOG2E;
    const float nb2 = -__ldg(beta)  * LOG2E;

    // ---- issue base-dot loads early (blocks 0..1023: one row per warp) ----
    const bool do_dot = (blockIdx.x < 1024);
    const int  dg     = blockIdx.x * 8 + warp;     // row id 0..8191
    float4 za0, za1, wv0, wv1;
    if (do_dot) {
        const float4* wr = (const float4*)w;
        const float4* zr = (const float4*)(z + (size_t)dg * DM);
        wv0 = __ldg(wr + lane * 2 + 0);
        wv1 = __ldg(wr + lane * 2 + 1);
        za0 = __ldg(zr + lane * 2 + 0);
        za1 = __ldg(zr + lane * 2 + 1);
    }

    // ---- build tile in smem from raw t/loc ----
    const int rowbase = rt * ROWS_PB;
    const int jbase   = jt * TJ;
    const float*  tb = t + (size_t)b * NLEN;
    const float2* lb = (const float2*)(loc + (size_t)b * NLEN * 2);

    if (tid < TJ) {
        const int j = jbase + tid;
        const float2 lj = __ldg(lb + j);
        const float  uj = nb2 * __ldg(tb + j);
        tile[tid] = make_float4(lj.x, lj.y, 0.0f, -uj);
    }
    __syncthreads();

    // ---- pair loop (R7 body) ----
    const int i = rowbase + tid;
    const float2 li = __ldg(lb + i);
    const float pix = li.x, piy = li.y;

    float a0 = 0.0f, a1 = 0.0f, a2 = 0.0f, a3 = 0.0f;

    if (jbase >= rowbase + ROWS_PB) {
        // interior tile: every j > every i, no masking
        #pragma unroll 4
        for (int jj = 0; jj < TJ; jj += 4) {
            const float4 v0 = tile[jj + 0];
            const float4 v1 = tile[jj + 1];
            const float4 v2 = tile[jj + 2];
            const float4 v3 = tile[jj + 3];
            a0 += pair_term(pix, piy, ng2, v0);
            a1 += pair_term(pix, piy, ng2, v1);
            a2 += pair_term(pix, piy, ng2, v2);
            a3 += pair_term(pix, piy, ng2, v3);
        }
    } else {
        // diagonal tile: keep only j > i
        const int joff = jbase - rowbase;
        for (int jj = 0; jj < TJ; jj += 4) {
            const float4 v0 = tile[jj + 0];
            const float4 v1 = tile[jj + 1];
            const float4 v2 = tile[jj + 2];
            const float4 v3 = tile[jj + 3];
            const float e0 = pair_term(pix, piy, ng2, v0);
            const float e1 = pair_term(pix, piy, ng2, v1);
            const float e2 = pair_term(pix, piy, ng2, v2);
            const float e3 = pair_term(pix, piy, ng2, v3);
            if (joff + jj + 0 > tid) a0 += e0;
            if (joff + jj + 1 > tid) a1 += e1;
            if (joff + jj + 2 > tid) a2 += e2;
            if (joff + jj + 3 > tid) a3 += e3;
        }
    }

    atomicAdd(g_excite + b * NLEN + i, (a0 + a1) + (a2 + a3));

    // ---- finish the base dot (z data long since arrived) ----
    if (do_dot) {
        float dotp;
        dotp = za0.x * wv0.x;
        dotp = fmaf(za0.y, wv0.y, dotp);
        dotp = fmaf(za0.z, wv0.z, dotp);
        dotp = fmaf(za0.w, wv0.w, dotp);
        dotp = fmaf(za1.x, wv1.x, dotp);
        dotp = fmaf(za1.y, wv1.y, dotp);
        dotp = fmaf(za1.z, wv1.z, dotp);
        dotp = fmaf(za1.w, wv1.w, dotp);
        #pragma unroll
        for (int off = 16; off > 0; off >>= 1)
            dotp += __shfl_xor_sync(0xffffffffu, dotp, off);
        if (lane == 0) g_base[dg] = dotp;
    }
}

// ---------------------------------------------------------------------------
// K2: combine. out[g] = mu + exp(dot+b) + alpha*(i+1) + alpha*2^{u_i}*excite.
// (alpha*(i+1) = closed form of the j<=i masked entries: triu mask applied
// BEFORE exp in the reference, so each contributes exp(0)*exp(0)=1.)
// Also re-zeroes g_excite so the next graph replay starts clean.
// ---------------------------------------------------------------------------
__global__ __launch_bounds__(256)
void hawkes_combine_kernel(const float* __restrict__ t,
                           const float* __restrict__ bias,
                           const float* __restrict__ mu,
                           const float* __restrict__ alpha,
                           const float* __restrict__ beta,
                           float* __restrict__ out)
{
    const int g = blockIdx.x * 256 + threadIdx.x;   // 0..8191
    const int i = g & (NLEN - 1);

    const float muv = __ldg(mu);
    const float av  = __ldg(alpha);
    const float bv  = __ldg(bias);
    const float nb2 = -__ldg(beta) * LOG2E;

    const float base  = ex2_approx((g_base[g] + bv) * LOG2E);
    const float ui    = nb2 * __ldg(t + g);
    const float exc   = g_excite[g];
    out[g] = muv + base + av * ((float)(i + 1) + ex2_approx(ui) * exc);
    g_excite[g] = 0.0f;
}

extern "C" void kernel_launch(void* const* d_in, const int* in_sizes, int n_in,
                              void* d_out, int out_size)
{
    const float* z     = (const float*)d_in[0];
    const float* t     = (const float*)d_in[1];
    const float* loc   = (const float*)d_in[2];
    const float* w     = (const float*)d_in[3];
    const float* bias  = (const float*)d_in[4];
    const float* mu    = (const float*)d_in[5];
    const float* alpha = (const float*)d_in[6];
    const float* beta  = (const float*)d_in[7];
    const float* gamma = (const float*)d_in[8];
    float* out = (float*)d_out;

    hawkes_fused_kernel<<<GRID_K1, 256>>>(z, t, loc, w, beta, gamma);
    hawkes_combine_kernel<<<32, 256>>>(t, bias, mu, alpha, beta, out);
}